// round 16
// baseline (speedup 1.0000x reference)
#include <cuda_runtime.h>

#define NN 100000
#define EE 3200000
#define E4 (EE / 4)

#define FX_S   32768.0f          // 2^15 fixed-point scale
#define FX_INV (1.0f / 32768.0f)
#define FX_C   (1u << 19)        // per-edge offset making halves non-negative

// Scratch (__device__ globals; zero-initialized at module load).
// INVARIANT: g_deg, g_acc, g_t are zero at entry to kernel_launch; k_final
// re-zeroes them after use so the invariant holds for the next call.
__device__ float                g_deg[NN];
__device__ float                g_dinv[NN];
__device__ float2               g_ab[NN];    // (dinv*x0, dinv*x1) f32 (self term)
__device__ unsigned long long   g_enc[NN];   // packed fixed-point (a,b)
__device__ unsigned long long   g_acc[NN];   // layer-1 accumulator (packed)
__device__ float                g_q[NN];
__device__ float                g_t[NN];

__device__ __forceinline__ void red_add_u64(unsigned long long* addr,
                                            unsigned long long v) {
    asm volatile("red.global.add.u64 [%0], %1;"
                 :: "l"(addr), "l"(v) : "memory");
}

// K1: degree count over edge destinations (col), int4, 2 per thread
__global__ void __launch_bounds__(256) k_deg(const int4* __restrict__ col4, int e4) {
    int i = (blockIdx.x * blockDim.x + threadIdx.x) * 2;
    #pragma unroll
    for (int u = 0; u < 2; u++) {
        int idx = i + u;
        if (idx < e4) {
            int4 c = __ldg(&col4[idx]);
            atomicAdd(&g_deg[c.x], 1.0f);
            atomicAdd(&g_deg[c.y], 1.0f);
            atomicAdd(&g_deg[c.z], 1.0f);
            atomicAdd(&g_deg[c.w], 1.0f);
        }
    }
}

// K2: per-node dinv = rsqrt(deg + 1 self-loop); (a,b) = dinv * x, stored as
// f32 pair (self term) AND packed offset-fixed-point u64 (scatter operand).
__global__ void __launch_bounds__(256) k_node1(const float* __restrict__ x, int n) {
    int i = blockIdx.x * blockDim.x + threadIdx.x;
    if (i < n) {
        float dinv = rsqrtf(g_deg[i] + 1.0f);
        float2 xi = ((const float2*)x)[i];
        float a = dinv * xi.x;
        float b = dinv * xi.y;
        g_dinv[i] = dinv;
        g_ab[i] = make_float2(a, b);
        unsigned int ea = (unsigned int)(int)rintf(a * FX_S) + FX_C;
        unsigned int eb = (unsigned int)(int)rintf(b * FX_S) + FX_C;
        g_enc[i] = ((unsigned long long)ea << 32) | (unsigned long long)eb;
    }
}

// K3: layer-1 edge scatter — one 8B gather + ONE u64 integer RED per edge
__global__ void __launch_bounds__(256) k_scatter1(const int4* __restrict__ row4,
                                                  const int4* __restrict__ col4, int e4) {
    int i = (blockIdx.x * blockDim.x + threadIdx.x) * 2;
    #pragma unroll
    for (int u = 0; u < 2; u++) {
        int idx = i + u;
        if (idx < e4) {
            int4 r = __ldg(&row4[idx]);
            int4 c = __ldg(&col4[idx]);
            unsigned long long v0 = __ldg(&g_enc[r.x]);
            unsigned long long v1 = __ldg(&g_enc[r.y]);
            unsigned long long v2 = __ldg(&g_enc[r.z]);
            unsigned long long v3 = __ldg(&g_enc[r.w]);
            red_add_u64(&g_acc[c.x], v0);
            red_add_u64(&g_acc[c.y], v1);
            red_add_u64(&g_acc[c.z], v2);
            red_add_u64(&g_acc[c.w], v3);
        }
    }
}

// K4: per-node MLP — decode packed sums, reconstruct h1, relu, dot W2.
// Two nodes per thread for ILP.
__global__ void __launch_bounds__(256) k_node2(const float* __restrict__ W1,
                                               const float* __restrict__ b1,
                                               const float* __restrict__ W2, int n) {
    __shared__ float sW10[64], sW11[64], sB1[64], sW2[64];
    int t = threadIdx.x;
    if (t < 64) {
        sW10[t] = W1[t];
        sW11[t] = W1[64 + t];
        sB1[t]  = b1[t];
        sW2[t]  = W2[t];
    }
    __syncthreads();
    int i0 = blockIdx.x * (blockDim.x * 2) + t;
    int i1 = i0 + blockDim.x;

    float dinv0 = 0.f, ca0 = 0.f, cb0 = 0.f;
    float dinv1 = 0.f, ca1 = 0.f, cb1 = 0.f;
    if (i0 < n) {
        dinv0 = g_dinv[i0];
        unsigned long long s = g_acc[i0];
        unsigned int cnt = (unsigned int)g_deg[i0];        // exact small int
        unsigned int off = cnt * FX_C;
        float2 self = g_ab[i0];
        ca0 = (float)(int)((unsigned int)(s >> 32) - off) * FX_INV + self.x;
        cb0 = (float)(int)((unsigned int) s        - off) * FX_INV + self.y;
    }
    if (i1 < n) {
        dinv1 = g_dinv[i1];
        unsigned long long s = g_acc[i1];
        unsigned int cnt = (unsigned int)g_deg[i1];
        unsigned int off = cnt * FX_C;
        float2 self = g_ab[i1];
        ca1 = (float)(int)((unsigned int)(s >> 32) - off) * FX_INV + self.x;
        cb1 = (float)(int)((unsigned int) s        - off) * FX_INV + self.y;
    }
    float p0 = 0.0f, p1 = 0.0f;
    #pragma unroll
    for (int j = 0; j < 64; j++) {
        float w0 = sW10[j], w1 = sW11[j], bb = sB1[j], w2 = sW2[j];
        float h0 = fmaf(dinv0, fmaf(ca0, w0, cb0 * w1), bb);
        float h1 = fmaf(dinv1, fmaf(ca1, w0, cb1 * w1), bb);
        h0 = fmaxf(h0, 0.0f);
        h1 = fmaxf(h1, 0.0f);
        p0 = fmaf(h0, w2, p0);
        p1 = fmaf(h1, w2, p1);
    }
    if (i0 < n) g_q[i0] = dinv0 * p0;
    if (i1 < n) g_q[i1] = dinv1 * p1;
}

// K5: layer-2 edge scatter — one 4B gather + one 4B RED per edge
__global__ void __launch_bounds__(256) k_scatter2(const int4* __restrict__ row4,
                                                  const int4* __restrict__ col4, int e4) {
    int i = (blockIdx.x * blockDim.x + threadIdx.x) * 2;
    #pragma unroll
    for (int u = 0; u < 2; u++) {
        int idx = i + u;
        if (idx < e4) {
            int4 r = __ldg(&row4[idx]);
            int4 c = __ldg(&col4[idx]);
            float q0 = __ldg(&g_q[r.x]);
            float q1 = __ldg(&g_q[r.y]);
            float q2 = __ldg(&g_q[r.z]);
            float q3 = __ldg(&g_q[r.w]);
            atomicAdd(&g_t[c.x], q0);
            atomicAdd(&g_t[c.y], q1);
            atomicAdd(&g_t[c.z], q2);
            atomicAdd(&g_t[c.w], q3);
        }
    }
}

// K6: final — emit output AND restore the zero-scratch invariant.
__global__ void __launch_bounds__(256) k_final(const float* __restrict__ b2,
                                               float* __restrict__ out, int n) {
    int i = blockIdx.x * blockDim.x + threadIdx.x;
    if (i < n) {
        out[i] = fmaf(g_dinv[i], g_t[i] + g_q[i], b2[0]);
        g_deg[i] = 0.0f;
        g_acc[i] = 0ull;
        g_t[i]   = 0.0f;
    }
}

extern "C" void kernel_launch(void* const* d_in, const int* in_sizes, int n_in,
                              void* d_out, int out_size) {
    const float* x   = (const float*)d_in[0];
    const int*   ei  = (const int*)d_in[1];
    const float* W1  = (const float*)d_in[2];
    const float* b1  = (const float*)d_in[3];
    const float* W2  = (const float*)d_in[4];
    const float* b2  = (const float*)d_in[5];
    float* out = (float*)d_out;

    const int n = NN;
    const int e4 = E4;
    const int4* row4 = (const int4*)ei;
    const int4* col4 = (const int4*)(ei + EE);

    const int TB = 256;
    const int gN  = (n + TB - 1) / TB;
    const int gN2 = (n + TB * 2 - 1) / (TB * 2);
    const int gE2 = (e4 / 2 + TB - 1) / TB;   // 2 int4 per thread

    k_deg     <<<gE2, TB>>>(col4, e4);
    k_node1   <<<gN, TB>>>(x, n);
    k_scatter1<<<gE2, TB>>>(row4, col4, e4);
    k_node2   <<<gN2, TB>>>(W1, b1, W2, n);
    k_scatter2<<<gE2, TB>>>(row4, col4, e4);
    k_final   <<<gN, TB>>>(b2, out, n);
}

// round 17
// speedup vs baseline: 1.0495x; 1.0495x over previous
#include <cuda_runtime.h>
#include <cuda_fp16.h>

#define NN 100000
#define EE 3200000
#define E4 (EE / 4)

// Scratch (__device__ globals; zero-initialized at module load).
// INVARIANT: g_deg, g_sab, g_t are zero at entry to kernel_launch; k_final
// re-zeroes them after use so the invariant holds for the next call.
__device__ float    g_deg[NN];
__device__ float    g_dinv[NN];
__device__ float2   g_ab[NN];    // (dinv*x0, dinv*x1) f32 — self-loop term
__device__ __half2  g_abh[NN];   // same pair packed fp16 — 4B scatter operand
__device__ float2   g_sab[NN];   // layer-1 accumulators (f32, exact adds)
__device__ float    g_q[NN];
__device__ float    g_t[NN];

__device__ __forceinline__ void red_add_v2(float2* addr, float a, float b) {
    asm volatile("red.global.add.v2.f32 [%0], {%1, %2};"
                 :: "l"(addr), "f"(a), "f"(b) : "memory");
}

// K1: degree count over edge destinations (col), int4, 2 per thread
__global__ void __launch_bounds__(256) k_deg(const int4* __restrict__ col4, int e4) {
    int i = (blockIdx.x * blockDim.x + threadIdx.x) * 2;
    #pragma unroll
    for (int u = 0; u < 2; u++) {
        int idx = i + u;
        if (idx < e4) {
            int4 c = __ldg(&col4[idx]);
            atomicAdd(&g_deg[c.x], 1.0f);
            atomicAdd(&g_deg[c.y], 1.0f);
            atomicAdd(&g_deg[c.z], 1.0f);
            atomicAdd(&g_deg[c.w], 1.0f);
        }
    }
}

// K2: per-node dinv = rsqrt(deg + 1 self-loop); (a,b) = dinv * x.
// Stored f32 (self term, exact) and half2 (4B scatter operand).
__global__ void __launch_bounds__(256) k_node1(const float* __restrict__ x, int n) {
    int i = blockIdx.x * blockDim.x + threadIdx.x;
    if (i < n) {
        float dinv = rsqrtf(g_deg[i] + 1.0f);
        float2 xi = ((const float2*)x)[i];
        float a = dinv * xi.x;
        float b = dinv * xi.y;
        g_dinv[i] = dinv;
        g_ab[i]  = make_float2(a, b);
        g_abh[i] = __floats2half2_rn(a, b);
    }
}

// K3: layer-1 edge scatter — one 4B half2 gather + one 8B v2.f32 RED per edge
__global__ void __launch_bounds__(256) k_scatter1(const int4* __restrict__ row4,
                                                  const int4* __restrict__ col4, int e4) {
    int i = (blockIdx.x * blockDim.x + threadIdx.x) * 2;
    #pragma unroll
    for (int u = 0; u < 2; u++) {
        int idx = i + u;
        if (idx < e4) {
            int4 r = __ldg(&row4[idx]);
            int4 c = __ldg(&col4[idx]);
            __half2 h0 = __ldg(&g_abh[r.x]);
            __half2 h1 = __ldg(&g_abh[r.y]);
            __half2 h2 = __ldg(&g_abh[r.z]);
            __half2 h3 = __ldg(&g_abh[r.w]);
            float2 v0 = __half22float2(h0);
            float2 v1 = __half22float2(h1);
            float2 v2 = __half22float2(h2);
            float2 v3 = __half22float2(h3);
            red_add_v2(&g_sab[c.x], v0.x, v0.y);
            red_add_v2(&g_sab[c.y], v1.x, v1.y);
            red_add_v2(&g_sab[c.z], v2.x, v2.y);
            red_add_v2(&g_sab[c.w], v3.x, v3.y);
        }
    }
}

// K4: per-node MLP — reconstruct h1 (64-wide), relu, dot W2 -> q = dinv * p
// Two nodes per thread for ILP. Self term added in f32 (exact).
__global__ void __launch_bounds__(256) k_node2(const float* __restrict__ W1,
                                               const float* __restrict__ b1,
                                               const float* __restrict__ W2, int n) {
    __shared__ float sW10[64], sW11[64], sB1[64], sW2[64];
    int t = threadIdx.x;
    if (t < 64) {
        sW10[t] = W1[t];
        sW11[t] = W1[64 + t];
        sB1[t]  = b1[t];
        sW2[t]  = W2[t];
    }
    __syncthreads();
    int i0 = blockIdx.x * (blockDim.x * 2) + t;
    int i1 = i0 + blockDim.x;

    float dinv0 = 0.f, ca0 = 0.f, cb0 = 0.f;
    float dinv1 = 0.f, ca1 = 0.f, cb1 = 0.f;
    if (i0 < n) {
        dinv0 = g_dinv[i0];
        float2 s = g_ab[i0], a = g_sab[i0];
        ca0 = a.x + s.x; cb0 = a.y + s.y;
    }
    if (i1 < n) {
        dinv1 = g_dinv[i1];
        float2 s = g_ab[i1], a = g_sab[i1];
        ca1 = a.x + s.x; cb1 = a.y + s.y;
    }
    float p0 = 0.0f, p1 = 0.0f;
    #pragma unroll
    for (int j = 0; j < 64; j++) {
        float w0 = sW10[j], w1 = sW11[j], bb = sB1[j], w2 = sW2[j];
        float h0 = fmaf(dinv0, fmaf(ca0, w0, cb0 * w1), bb);
        float h1 = fmaf(dinv1, fmaf(ca1, w0, cb1 * w1), bb);
        h0 = fmaxf(h0, 0.0f);
        h1 = fmaxf(h1, 0.0f);
        p0 = fmaf(h0, w2, p0);
        p1 = fmaf(h1, w2, p1);
    }
    if (i0 < n) g_q[i0] = dinv0 * p0;
    if (i1 < n) g_q[i1] = dinv1 * p1;
}

// K5: layer-2 edge scatter — one 4B gather + one 4B RED per edge
__global__ void __launch_bounds__(256) k_scatter2(const int4* __restrict__ row4,
                                                  const int4* __restrict__ col4, int e4) {
    int i = (blockIdx.x * blockDim.x + threadIdx.x) * 2;
    #pragma unroll
    for (int u = 0; u < 2; u++) {
        int idx = i + u;
        if (idx < e4) {
            int4 r = __ldg(&row4[idx]);
            int4 c = __ldg(&col4[idx]);
            float q0 = __ldg(&g_q[r.x]);
            float q1 = __ldg(&g_q[r.y]);
            float q2 = __ldg(&g_q[r.z]);
            float q3 = __ldg(&g_q[r.w]);
            atomicAdd(&g_t[c.x], q0);
            atomicAdd(&g_t[c.y], q1);
            atomicAdd(&g_t[c.z], q2);
            atomicAdd(&g_t[c.w], q3);
        }
    }
}

// K6: final — emit output AND restore the zero-scratch invariant.
__global__ void __launch_bounds__(256) k_final(const float* __restrict__ b2,
                                               float* __restrict__ out, int n) {
    int i = blockIdx.x * blockDim.x + threadIdx.x;
    if (i < n) {
        out[i] = fmaf(g_dinv[i], g_t[i] + g_q[i], b2[0]);
        g_deg[i] = 0.0f;
        g_sab[i] = make_float2(0.0f, 0.0f);
        g_t[i]   = 0.0f;
    }
}

extern "C" void kernel_launch(void* const* d_in, const int* in_sizes, int n_in,
                              void* d_out, int out_size) {
    const float* x   = (const float*)d_in[0];
    const int*   ei  = (const int*)d_in[1];
    const float* W1  = (const float*)d_in[2];
    const float* b1  = (const float*)d_in[3];
    const float* W2  = (const float*)d_in[4];
    const float* b2  = (const float*)d_in[5];
    float* out = (float*)d_out;

    const int n = NN;
    const int e4 = E4;
    const int4* row4 = (const int4*)ei;
    const int4* col4 = (const int4*)(ei + EE);

    const int TB = 256;
    const int gN  = (n + TB - 1) / TB;
    const int gN2 = (n + TB * 2 - 1) / (TB * 2);
    const int gE2 = (e4 / 2 + TB - 1) / TB;   // 2 int4 per thread

    k_deg     <<<gE2, TB>>>(col4, e4);
    k_node1   <<<gN, TB>>>(x, n);
    k_scatter1<<<gE2, TB>>>(row4, col4, e4);
    k_node2   <<<gN2, TB>>>(W1, b1, W2, n);
    k_scatter2<<<gE2, TB>>>(row4, col4, e4);
    k_final   <<<gN, TB>>>(b2, out, n);
}